// round 13
// baseline (speedup 1.0000x reference)
#include <cuda_runtime.h>

typedef unsigned long long ull;
#define FULLM 0xffffffffu

// ---------------- device scratch (no allocations allowed) ----------------
__device__ int   g_order[1024];   // batch ids sorted by len descending
__device__ float g_res[1024];     // per-rank results

// ---------------- f32x2 helpers (sm_103a packed fp32 path) ---------------
__device__ __forceinline__ ull pk2(float lo, float hi) {
    ull r; asm("mov.b64 %0,{%1,%2};" : "=l"(r) : "f"(lo), "f"(hi)); return r;
}
__device__ __forceinline__ float2 upk2(ull v) {
    float2 f; asm("mov.b64 {%0,%1},%2;" : "=f"(f.x), "=f"(f.y) : "l"(v)); return f;
}
__device__ __forceinline__ ull ffma2(ull a, ull b, ull c) {
    ull d; asm("fma.rn.f32x2 %0,%1,%2,%3;" : "=l"(d) : "l"(a), "l"(b), "l"(c)); return d;
}

// ---------------- prep: rank batches by length (desc) --------------------
__global__ void prep_kernel(const int* __restrict__ lens) {
    const int lane = threadIdx.x & 31;
    const int warp = threadIdx.x >> 5;
    const int b    = blockIdx.x * 8 + warp;
    const int len  = __ldg(&lens[b]);
    int rank = 0;
#pragma unroll
    for (int k = 0; k < 32; k++) {
        const int i  = k * 32 + lane;
        const int li = __ldg(&lens[i]);
        rank += (li > len) || ((li == len) && (i < b));
    }
    rank += __shfl_xor_sync(FULLM, rank, 16);
    rank += __shfl_xor_sync(FULLM, rank, 8);
    rank += __shfl_xor_sync(FULLM, rank, 4);
    rank += __shfl_xor_sync(FULLM, rank, 2);
    rank += __shfl_xor_sync(FULLM, rank, 1);
    if (lane == 0) g_order[rank] = b;
}

// ---------------- main CRF kernel ----------------------------------------
// R11 evidence: wall = len_max(512) x per-step chain (~290cyc); step body is
// at its floor. This version halves the RECURRENCE: partition = s^T
// Prod_t(diag(p_t)E) e_start is associative -> split at m=len/2. Forward
// warp computes alpha_m (m matvecs, E); backward warp concurrently computes
// beta_m (len-m matvecs with E^T, c_t = (E^T c_{t+1}) (x) p_t, + one final
// zero-logit matvec); Z = M_f+M_b+log(alpha_m . beta_m).
// 148 blocks x 384 thr (12 warps): warps 0-4 fwd / 5-9 bwd of the 5 LONGEST
// remaining ranks (blk*5+p, p<5 -> ranks 0..739 split); warps 10-11 run
// ranks 740..1023 single-direction (short: len < 256). Wall ~ 257 steps.
__global__ __launch_bounds__(384, 1) void crf_kernel(
    const float* __restrict__ logits,   // [1024,512,50]
    const float* __restrict__ tr,       // [50,50]
    const int*   __restrict__ labels,   // [1024,512]
    const int*   __restrict__ lens)     // [1024]
{
    __shared__ __align__(16) float vbuf[12][2][64]; // [warp][dblbuf][state]
    __shared__ float cvec[5][64];                   // fwd alpha_m vectors
    __shared__ float cscal[5][3];                   // fwd {M, em, trn}

    const int lane = threadIdx.x & 31;
    const int warp = threadIdx.x >> 5;

    const bool isB = (warp >= 5) && (warp < 10);    // backward half
    const bool isS = (warp >= 10);                  // single (short seq)
    const int  pair = isB ? (warp - 5) : warp;      // valid for warp<10
    const int  rank = (warp < 10) ? (blockIdx.x * 5 + pair)
                                  : (740 + blockIdx.x * 2 + (warp - 10));
    const bool active = (rank < 1024);
    const int  b    = g_order[active ? rank : 0];
    const int  len  = lens[b];
    const int  base = b * 512;
    const int  m    = isS ? (active ? len : 0) : (len >> 1);

    const int  j0  = 2 * lane;           // this lane owns states j0, j0+1
    const bool vl  = (lane < 25);
    const int  j0c = vl ? j0 : 0;        // clamped col for unguarded loads

    // ---- matrix in regs: fwd/single = E rows; bwd = E^T rows (E cols) ---
    ull E0[25], E1[25];
#pragma unroll
    for (int k = 0; k < 25; k++) {
        float e00 = 0.f, e01 = 0.f, e10 = 0.f, e11 = 0.f;
        if (vl) {
            if (!isB) {
                float2 r0 = *(const float2*)&tr[ j0      * 50 + 2 * k];
                float2 r1 = *(const float2*)&tr[(j0 + 1) * 50 + 2 * k];
                e00 = __expf(r0.x); e01 = __expf(r0.y);
                e10 = __expf(r1.x); e11 = __expf(r1.y);
            } else {
                e00 = __expf(tr[(2 * k    ) * 50 + j0    ]);
                e01 = __expf(tr[(2 * k + 1) * 50 + j0    ]);
                e10 = __expf(tr[(2 * k    ) * 50 + j0 + 1]);
                e11 = __expf(tr[(2 * k + 1) * 50 + j0 + 1]);
            }
        }
        E0[k] = pk2(e00, e01);
        E1[k] = pk2(e10, e11);
    }
    const float Es0 = vl ? __expf(tr[49 * 50 + j0])     : 0.f; // exp(tr[stop,j])
    const float Es1 = vl ? __expf(tr[49 * 50 + j0 + 1]) : 0.f;

    // ---- init buffer 0 ---------------------------------------------------
    vbuf[warp][0][lane] = 0.f; vbuf[warp][0][lane + 32] = 0.f;
    __syncwarp();
    if (!isB && lane == 24) vbuf[warp][0][48] = 1.f;   // onehot(start)
    __syncwarp();

    float M = 0.f, em = 0.f, trn = 0.f;
    int   hist = isB ? 49 : 48;          // bwd: lab_{t+1} (init stop); fwd: lab_{t-1} (init start)
    float u0 = (!isB && lane == 24) ? 1.f : 0.f;       // alpha_0 if m==0
    float u1 = 0.f;

    // ---- prefetch queue (4 slots, direction-aware preload) ---------------
    float2 lgq[4]; int lbq[4];
#pragma unroll
    for (int s = 0; s < 4; s++) {
        int tt = isB ? (len - 1 - s) : s;
        tt = max(0, min(tt, len - 1));
        lgq[s] = *(const float2*)&logits[(base + tt) * 50 + j0c];
        lbq[s] = __ldg(&labels[base + tt]);
    }

    const ull z = pk2(0.f, 0.f);

    // one matvec step; rb literal at every call site
    auto fstep = [&](int rb, float2 lg, int lab, bool first, float fscale, bool bdir) {
        const ulonglong2* vs = (const ulonglong2*)&vbuf[warp][rb][0];
        ull A0 = z, A1 = z, A2 = z, A3 = z, B0 = z, B1 = z, B2 = z, B3 = z;
        float v0n;
        {
            ulonglong2 va = vs[0]; v0n = upk2(va.x).x;   // v[0] = normalizer
            ulonglong2 vb = vs[1];
            A0 = ffma2(E0[0], va.x, A0); A1 = ffma2(E0[1], va.y, A1);
            A2 = ffma2(E0[2], vb.x, A2); A3 = ffma2(E0[3], vb.y, A3);
            B0 = ffma2(E1[0], va.x, B0); B1 = ffma2(E1[1], va.y, B1);
            B2 = ffma2(E1[2], vb.x, B2); B3 = ffma2(E1[3], vb.y, B3);
        }
#pragma unroll
        for (int k = 4; k < 24; k += 4) {
            ulonglong2 va = vs[k >> 1], vb = vs[(k >> 1) + 1];
            A0 = ffma2(E0[k],     va.x, A0); A1 = ffma2(E0[k + 1], va.y, A1);
            A2 = ffma2(E0[k + 2], vb.x, A2); A3 = ffma2(E0[k + 3], vb.y, A3);
            B0 = ffma2(E1[k],     va.x, B0); B1 = ffma2(E1[k + 1], va.y, B1);
            B2 = ffma2(E1[k + 2], vb.x, B2); B3 = ffma2(E1[k + 3], vb.y, B3);
        }
        { ull vt = vs[12].x; A0 = ffma2(E0[24], vt, A0); B0 = ffma2(E1[24], vt, B0); }

        const float logr = first ? 0.f : __logf(v0n);    // off-chain vs FFMA
        M += logr;
        const float px = __expf(lg.x - logr);
        const float py = __expf(lg.y - logr);
        em += fscale * (((lab >> 1) == lane) ? ((lab & 1) ? lg.y : lg.x) : 0.f);
        const int ti = bdir ? (hist * 50 + lab) : (lab * 50 + hist);
        trn += fscale * __ldg(&tr[ti]);
        hist = lab;                                       // stale on final bwd step: unused

        float2 a0 = upk2(A0), a1 = upk2(A1), a2 = upk2(A2), a3 = upk2(A3);
        float2 b0 = upk2(B0), b1 = upk2(B1), b2 = upk2(B2), b3 = upk2(B3);
        const float S0 = ((a0.x + a0.y) + (a1.x + a1.y)) + ((a2.x + a2.y) + (a3.x + a3.y));
        const float S1 = ((b0.x + b0.y) + (b1.x + b1.y)) + ((b2.x + b2.y) + (b3.x + b3.y));
        u0 = S0 * px; u1 = S1 * py;
        *(float2*)&vbuf[warp][rb ^ 1][j0] = make_float2(u0, u1);
        __syncwarp();
    };

    if (!isB) {
        // ---------------- FORWARD / SINGLE: m steps ascending -------------
        const int full = m & ~3;
        for (int t0 = 0; t0 < full; t0 += 4) {
            { float2 lg = lgq[0]; int lab = lbq[0];
              int tt = min(t0 + 4, len - 1);
              lgq[0] = *(const float2*)&logits[(base + tt) * 50 + j0c];
              lbq[0] = __ldg(&labels[base + tt]);
              fstep(0, lg, lab, t0 == 0, 1.f, false); }
            { float2 lg = lgq[1]; int lab = lbq[1];
              int tt = min(t0 + 5, len - 1);
              lgq[1] = *(const float2*)&logits[(base + tt) * 50 + j0c];
              lbq[1] = __ldg(&labels[base + tt]);
              fstep(1, lg, lab, false, 1.f, false); }
            { float2 lg = lgq[2]; int lab = lbq[2];
              int tt = min(t0 + 6, len - 1);
              lgq[2] = *(const float2*)&logits[(base + tt) * 50 + j0c];
              lbq[2] = __ldg(&labels[base + tt]);
              fstep(0, lg, lab, false, 1.f, false); }
            { float2 lg = lgq[3]; int lab = lbq[3];
              int tt = min(t0 + 7, len - 1);
              lgq[3] = *(const float2*)&logits[(base + tt) * 50 + j0c];
              lbq[3] = __ldg(&labels[base + tt]);
              fstep(1, lg, lab, false, 1.f, false); }
        }
        if (full + 0 < m) fstep(0, lgq[0], lbq[0], full == 0, 1.f, false);
        if (full + 1 < m) fstep(1, lgq[1], lbq[1], false, 1.f, false);
        if (full + 2 < m) fstep(0, lgq[2], lbq[2], false, 1.f, false);

        if (isS) {
            if (active) {
                trn += __ldg(&tr[49 * 50 + hist]);        // stop term
                float w = u0 * Es0 + u1 * Es1;
                float e = em;
                w += __shfl_xor_sync(FULLM, w, 16); e += __shfl_xor_sync(FULLM, e, 16);
                w += __shfl_xor_sync(FULLM, w, 8);  e += __shfl_xor_sync(FULLM, e, 8);
                w += __shfl_xor_sync(FULLM, w, 4);  e += __shfl_xor_sync(FULLM, e, 4);
                w += __shfl_xor_sync(FULLM, w, 2);  e += __shfl_xor_sync(FULLM, e, 2);
                w += __shfl_xor_sync(FULLM, w, 1);  e += __shfl_xor_sync(FULLM, e, 1);
                if (lane == 0) g_res[rank] = (M + __logf(w)) - e - trn;
            }
        } else {
            // boundary transition term t=m (fwd owns transitions 0..m)
            const int labM = __ldg(&labels[base + m]);    // m < len always
            trn += __ldg(&tr[labM * 50 + hist]);
            float e = em;
            e += __shfl_xor_sync(FULLM, e, 16);
            e += __shfl_xor_sync(FULLM, e, 8);
            e += __shfl_xor_sync(FULLM, e, 4);
            e += __shfl_xor_sync(FULLM, e, 2);
            e += __shfl_xor_sync(FULLM, e, 1);
            cvec[pair][j0] = u0; cvec[pair][j0 + 1] = u1; // alpha_m (lanes>=25: 0)
            if (lane == 0) { cscal[pair][0] = M; cscal[pair][1] = e; cscal[pair][2] = trn; }
        }
    } else {
        // ---------------- BACKWARD: init + (len-1-m) steps + final --------
        {   // init: c_{len-1} = s (x) p_{len-1}; consumes queue slot 0
            float2 lg = lgq[0]; int lab = lbq[0];
            int tt = max(len - 5, 0);
            lgq[0] = *(const float2*)&logits[(base + tt) * 50 + j0c];
            lbq[0] = __ldg(&labels[base + tt]);
            const float px = __expf(lg.x), py = __expf(lg.y);
            u0 = Es0 * px; u1 = Es1 * py;
            em += ((lab >> 1) == lane) ? ((lab & 1) ? lg.y : lg.x) : 0.f;
            trn += __ldg(&tr[hist * 50 + lab]);           // tr[stop, lab_{len-1}]
            hist = lab;
            *(float2*)&vbuf[warp][0][j0] = make_float2(u0, u1);
            __syncwarp();
        }
        const int nb    = len - 1 - m;    // final (zero-logit) matvec at kk==nb
        const int trips = nb + 1;
        const int full  = trips & ~3;
        for (int k0 = 0; k0 < full; k0 += 4) {
            { const int kk = k0 + 0; const bool fin = (kk == nb);
              float2 lg = fin ? make_float2(0.f, 0.f) : lgq[1];
              int lab = fin ? 0 : lbq[1];
              int tt = max(len - 6 - kk, 0);
              lgq[1] = *(const float2*)&logits[(base + tt) * 50 + j0c];
              lbq[1] = __ldg(&labels[base + tt]);
              fstep(0, lg, lab, false, fin ? 0.f : 1.f, true); }
            { const int kk = k0 + 1; const bool fin = (kk == nb);
              float2 lg = fin ? make_float2(0.f, 0.f) : lgq[2];
              int lab = fin ? 0 : lbq[2];
              int tt = max(len - 6 - kk, 0);
              lgq[2] = *(const float2*)&logits[(base + tt) * 50 + j0c];
              lbq[2] = __ldg(&labels[base + tt]);
              fstep(1, lg, lab, false, fin ? 0.f : 1.f, true); }
            { const int kk = k0 + 2; const bool fin = (kk == nb);
              float2 lg = fin ? make_float2(0.f, 0.f) : lgq[3];
              int lab = fin ? 0 : lbq[3];
              int tt = max(len - 6 - kk, 0);
              lgq[3] = *(const float2*)&logits[(base + tt) * 50 + j0c];
              lbq[3] = __ldg(&labels[base + tt]);
              fstep(0, lg, lab, false, fin ? 0.f : 1.f, true); }
            { const int kk = k0 + 3; const bool fin = (kk == nb);
              float2 lg = fin ? make_float2(0.f, 0.f) : lgq[0];
              int lab = fin ? 0 : lbq[0];
              int tt = max(len - 6 - kk, 0);
              lgq[0] = *(const float2*)&logits[(base + tt) * 50 + j0c];
              lbq[0] = __ldg(&labels[base + tt]);
              fstep(1, lg, lab, false, fin ? 0.f : 1.f, true); }
        }
        if (full + 0 < trips) { const bool fin = (full + 0 == nb);
            fstep(0, fin ? make_float2(0.f, 0.f) : lgq[1], fin ? 0 : lbq[1],
                  false, fin ? 0.f : 1.f, true); }
        if (full + 1 < trips) { const bool fin = (full + 1 == nb);
            fstep(1, fin ? make_float2(0.f, 0.f) : lgq[2], fin ? 0 : lbq[2],
                  false, fin ? 0.f : 1.f, true); }
        if (full + 2 < trips) { const bool fin = (full + 2 == nb);
            fstep(0, fin ? make_float2(0.f, 0.f) : lgq[3], fin ? 0 : lbq[3],
                  false, fin ? 0.f : 1.f, true); }
        // u0,u1 now hold beta_m
    }

    __syncthreads();

    if (isB) {
        // combine: Z = M_f + M_b + log(alpha_m . beta_m) - em - trn
        const float a0 = cvec[pair][j0], a1 = cvec[pair][j0 + 1];
        float w = u0 * a0 + u1 * a1;
        float e = em;
        w += __shfl_xor_sync(FULLM, w, 16); e += __shfl_xor_sync(FULLM, e, 16);
        w += __shfl_xor_sync(FULLM, w, 8);  e += __shfl_xor_sync(FULLM, e, 8);
        w += __shfl_xor_sync(FULLM, w, 4);  e += __shfl_xor_sync(FULLM, e, 4);
        w += __shfl_xor_sync(FULLM, w, 2);  e += __shfl_xor_sync(FULLM, e, 2);
        w += __shfl_xor_sync(FULLM, w, 1);  e += __shfl_xor_sync(FULLM, e, 1);
        if (lane == 0) {
            g_res[rank] = (cscal[pair][0] + M + __logf(w))
                        - (cscal[pair][1] + e) - (cscal[pair][2] + trn);
        }
    }
}

// ---------------- deterministic final reduction ---------------------------
__global__ void reduce_kernel(float* __restrict__ out) {
    __shared__ float s[512];
    int i = threadIdx.x;
    s[i] = g_res[i] + g_res[i + 512];
    __syncthreads();
    for (int off = 256; off > 0; off >>= 1) {
        if (i < off) s[i] += s[i + off];
        __syncthreads();
    }
    if (i == 0) *out = s[0] * (1.0f / 1024.0f);
}

// ---------------- launch ---------------------------------------------------
extern "C" void kernel_launch(void* const* d_in, const int* in_sizes, int n_in,
                              void* d_out, int out_size) {
    const float* logits = (const float*)d_in[0];
    const float* trans  = (const float*)d_in[1];
    const int*   labels = (const int*)d_in[2];
    const int*   lens   = (const int*)d_in[3];
    float*       out    = (float*)d_out;

    prep_kernel<<<128, 256>>>(lens);
    crf_kernel<<<148, 384>>>(logits, trans, labels, lens);
    reduce_kernel<<<1, 512>>>(out);
}